// round 1
// baseline (speedup 1.0000x reference)
#include <cuda_runtime.h>

#define HIDDEN    128
#define MAX_NODES 100000

// Scratch (no device allocation allowed): per-node precomputed projections,
// collapsed weights, collapsed bias, and the index-dtype flag.
__device__ float4 g_P[MAX_NODES];          // {src·A0, src·A1, dst·B0, dst·B1} per node
__device__ float  g_A0[HIDDEN], g_A1[HIDDEN], g_B0[HIDDEN], g_B1[HIDDEN];
__device__ float  g_bc[2];
__device__ int    g_is64;

// ---------------------------------------------------------------------------
// Kernel A: collapse the two linear layers.
//   Wc = W1 @ W2  (256 x 2),  bc = b1 @ W2 + b2  (2)
// One warp per output element (514 warps). Also probes the edges buffer to
// decide whether indices are stored as int64 or int32.
// ---------------------------------------------------------------------------
__global__ void combine_kernel(const float* __restrict__ W1,
                               const float* __restrict__ b1,
                               const float* __restrict__ W2,
                               const float* __restrict__ b2,
                               const long long* __restrict__ edges_as_i64,
                               int n_edges)
{
    int warp = (blockIdx.x * blockDim.x + threadIdx.x) >> 5;
    int lane = threadIdx.x & 31;

    if (warp < 512) {
        // Wc[i][j] = sum_k W1[i][k] * W2[k][j],  i in [0,256), j in {0,1}
        int i = warp >> 1;
        int j = warp & 1;
        float acc = 0.f;
        #pragma unroll 4
        for (int k = lane; k < 4 * HIDDEN; k += 32)
            acc += W1[i * (4 * HIDDEN) + k] * W2[k * 2 + j];
        #pragma unroll
        for (int o = 16; o; o >>= 1) acc += __shfl_xor_sync(0xffffffffu, acc, o);
        if (lane == 0) {
            float* dst = (i < HIDDEN) ? (j ? g_A1 : g_A0) : (j ? g_B1 : g_B0);
            dst[i & (HIDDEN - 1)] = acc;
        }
    } else if (warp < 514) {
        int j = warp - 512;
        float acc = 0.f;
        for (int k = lane; k < 4 * HIDDEN; k += 32)
            acc += b1[k] * W2[k * 2 + j];
        #pragma unroll
        for (int o = 16; o; o >>= 1) acc += __shfl_xor_sync(0xffffffffu, acc, o);
        if (lane == 0) g_bc[j] = acc + b2[j];
    } else if (warp == 514 && lane == 0) {
        // Dtype probe: reading an int32 buffer as int64 pairs (lo = index,
        // hi = next index) gives values >= 2^32 unless the neighbor is 0.
        // 64 consecutive "valid" int64 reads => genuinely int64.
        int probe = n_edges >= 64 ? 64 : (n_edges > 0 ? n_edges : 0);
        int ok64 = 1;
        for (int t = 0; t < probe; ++t) {
            long long v = edges_as_i64[t];
            if (v < 0 || v >= (long long)MAX_NODES) { ok64 = 0; break; }
        }
        g_is64 = ok64;
    }
}

// ---------------------------------------------------------------------------
// Kernel B: per-node precompute. One warp per node; lane l owns features
// [4l, 4l+4). Streams 51.2 MB of features once (HBM-bound phase).
// ---------------------------------------------------------------------------
__global__ void __launch_bounds__(256) node_kernel(const float* __restrict__ feat,
                                                   int n_nodes)
{
    __shared__ float sA0[HIDDEN], sA1[HIDDEN], sB0[HIDDEN], sB1[HIDDEN];
    int tid = threadIdx.x;
    if (tid < HIDDEN) {
        sA0[tid] = g_A0[tid];
        sA1[tid] = g_A1[tid];
        sB0[tid] = g_B0[tid];
        sB1[tid] = g_B1[tid];
    }
    __syncthreads();

    int warp = tid >> 5;
    int lane = tid & 31;
    int node = blockIdx.x * 8 + warp;
    if (node >= n_nodes) return;

    const float4* f4 = reinterpret_cast<const float4*>(feat + (size_t)node * HIDDEN);
    float4 x = f4[lane];              // coalesced: 32 lanes cover the 128-float row
    int k = lane * 4;

    float a0 = x.x * sA0[k] + x.y * sA0[k + 1] + x.z * sA0[k + 2] + x.w * sA0[k + 3];
    float a1 = x.x * sA1[k] + x.y * sA1[k + 1] + x.z * sA1[k + 2] + x.w * sA1[k + 3];
    float c0 = x.x * sB0[k] + x.y * sB0[k + 1] + x.z * sB0[k + 2] + x.w * sB0[k + 3];
    float c1 = x.x * sB1[k] + x.y * sB1[k + 1] + x.z * sB1[k + 2] + x.w * sB1[k + 3];

    #pragma unroll
    for (int o = 16; o; o >>= 1) {
        a0 += __shfl_xor_sync(0xffffffffu, a0, o);
        a1 += __shfl_xor_sync(0xffffffffu, a1, o);
        c0 += __shfl_xor_sync(0xffffffffu, c0, o);
        c1 += __shfl_xor_sync(0xffffffffu, c1, o);
    }
    if (lane == 0) g_P[node] = make_float4(a0, a1, c0, c1);
}

// ---------------------------------------------------------------------------
// Kernel C: per-edge gather + 2-class softmax. g_P (1.6 MB) is L2-resident,
// so the random gathers are L2 hits; HBM traffic is edges + output only.
// ---------------------------------------------------------------------------
__global__ void __launch_bounds__(256) edge_kernel(const void* __restrict__ edges,
                                                   float2* __restrict__ out,
                                                   int n_edges)
{
    int e = blockIdx.x * blockDim.x + threadIdx.x;
    if (e >= n_edges) return;

    int s, d;
    if (g_is64) {
        const long long* E = (const long long*)edges;
        s = (int)E[e];
        d = (int)E[e + n_edges];
    } else {
        const int* E = (const int*)edges;
        s = E[e];
        d = E[e + n_edges];
    }

    float4 ps = __ldg(&g_P[s]);
    float4 pd = __ldg(&g_P[d]);
    float l0 = ps.x + pd.z + g_bc[0];
    float l1 = ps.y + pd.w + g_bc[1];

    float m  = fmaxf(l0, l1);
    float e0 = expf(l0 - m);
    float e1 = expf(l1 - m);
    float inv = 1.0f / (e0 + e1);
    out[e] = make_float2(e0 * inv, e1 * inv);
}

// ---------------------------------------------------------------------------
// Launch: metadata order is
//   0: node_features_after_gcn (float32, N_NODES*128)
//   1: edges                   (int64 or int32, 2*N_EDGES)
//   2: W1 (256*512)  3: b1 (512)  4: W2 (512*2)  5: b2 (2)
// ---------------------------------------------------------------------------
extern "C" void kernel_launch(void* const* d_in, const int* in_sizes, int n_in,
                              void* d_out, int out_size)
{
    const float* feat  = (const float*)d_in[0];
    const void*  edges = d_in[1];
    const float* W1    = (const float*)d_in[2];
    const float* b1    = (const float*)d_in[3];
    const float* W2    = (const float*)d_in[4];
    const float* b2    = (const float*)d_in[5];

    int n_nodes = in_sizes[0] / HIDDEN;
    if (n_nodes > MAX_NODES) n_nodes = MAX_NODES;
    int n_edges = in_sizes[1] / 2;

    // A: collapse weights + dtype probe. 515 warps.
    combine_kernel<<<(515 * 32 + 255) / 256, 256>>>(
        W1, b1, W2, b2, (const long long*)edges, n_edges);

    // B: per-node projections. 8 nodes per 256-thread block.
    node_kernel<<<(n_nodes + 7) / 8, 256>>>(feat, n_nodes);

    // C: per-edge gather + softmax.
    edge_kernel<<<(n_edges + 255) / 256, 256>>>(edges, (float2*)d_out, n_edges);
}

// round 3
// speedup vs baseline: 1.2465x; 1.2465x over previous
#include <cuda_runtime.h>

#define HIDDEN    128
#define MAX_NODES 100000

// Scratch (no device allocation allowed).
__device__ float4 g_P[MAX_NODES];          // {n·A0, n·A1, n·B0, n·B1} per node
__device__ float  g_A0[HIDDEN], g_A1[HIDDEN], g_B0[HIDDEN], g_B1[HIDDEN];
__device__ float  g_bc[2];
__device__ int    g_is64;

// ---------------------------------------------------------------------------
// Kernel A: collapse the two linear layers.
//   Wc = W1 @ W2  (256 x 2),  bc = b1 @ W2 + b2  (2)
// One warp per output element (514 warps). Warp 514 runs a WARP-PARALLEL
// dtype probe on the edges buffer (the R1 serial probe cost 12 us).
// ---------------------------------------------------------------------------
__global__ void combine_kernel(const float* __restrict__ W1,
                               const float* __restrict__ b1,
                               const float* __restrict__ W2,
                               const float* __restrict__ b2,
                               const long long* __restrict__ edges_as_i64,
                               int n_edges)
{
    int warp = (blockIdx.x * blockDim.x + threadIdx.x) >> 5;
    int lane = threadIdx.x & 31;

    if (warp < 512) {
        // Wc[i][j] = sum_k W1[i][k] * W2[k][j],  i in [0,256), j in {0,1}
        int i = warp >> 1;
        int j = warp & 1;
        float acc = 0.f;
        #pragma unroll
        for (int k = lane; k < 4 * HIDDEN; k += 32)
            acc += W1[i * (4 * HIDDEN) + k] * W2[k * 2 + j];
        #pragma unroll
        for (int o = 16; o; o >>= 1) acc += __shfl_xor_sync(0xffffffffu, acc, o);
        if (lane == 0) {
            float* dst = (i < HIDDEN) ? (j ? g_A1 : g_A0) : (j ? g_B1 : g_B0);
            dst[i & (HIDDEN - 1)] = acc;
        }
    } else if (warp < 514) {
        int j = warp - 512;
        float acc = 0.f;
        #pragma unroll
        for (int k = lane; k < 4 * HIDDEN; k += 32)
            acc += b1[k] * W2[k * 2 + j];
        #pragma unroll
        for (int o = 16; o; o >>= 1) acc += __shfl_xor_sync(0xffffffffu, acc, o);
        if (lane == 0) g_bc[j] = acc + b2[j];
    } else if (warp == 514) {
        // Warp-parallel dtype probe: interpret the buffer as int64. If it is
        // really int32 indices, the hi word of each pair is the next index —
        // values land >= 2^32 (or the pattern fails range check) almost surely
        // across 64 samples. All 64 in-range => genuinely int64.
        int ok = 1;
        #pragma unroll
        for (int r = 0; r < 2; ++r) {
            int t = r * 32 + lane;
            if (t < n_edges) {
                long long v = edges_as_i64[t];
                if (v < 0 || v >= (long long)MAX_NODES) ok = 0;
            }
        }
        ok = __all_sync(0xffffffffu, ok);
        if (lane == 0) g_is64 = ok;
    }
}

// ---------------------------------------------------------------------------
// Kernel B: per-node precompute. Each warp handles 4 nodes with all 4 row
// loads issued up front (MLP=4). Lane l owns features [4l, 4l+4).
// Streams 51.2 MB of features once — the HBM-bound phase.
// ---------------------------------------------------------------------------
#define NODES_PER_WARP 4
#define WARPS_PER_BLOCK 8
#define NODES_PER_BLOCK (NODES_PER_WARP * WARPS_PER_BLOCK)

__global__ void __launch_bounds__(256) node_kernel(const float* __restrict__ feat,
                                                   int n_nodes)
{
    __shared__ float sA0[HIDDEN], sA1[HIDDEN], sB0[HIDDEN], sB1[HIDDEN];
    int tid = threadIdx.x;
    if (tid < HIDDEN) {
        sA0[tid] = g_A0[tid];
        sA1[tid] = g_A1[tid];
        sB0[tid] = g_B0[tid];
        sB1[tid] = g_B1[tid];
    }
    __syncthreads();

    int warp = tid >> 5;
    int lane = tid & 31;
    int node0 = blockIdx.x * NODES_PER_BLOCK + warp * NODES_PER_WARP;

    // Batch the 4 row loads up front (independent LDG.128s in flight).
    float4 x[NODES_PER_WARP];
    #pragma unroll
    for (int r = 0; r < NODES_PER_WARP; ++r) {
        int node = node0 + r;
        if (node < n_nodes) {
            const float4* f4 = reinterpret_cast<const float4*>(feat + (size_t)node * HIDDEN);
            x[r] = f4[lane];
        }
    }

    int k = lane * 4;
    float wa0x = sA0[k], wa0y = sA0[k+1], wa0z = sA0[k+2], wa0w = sA0[k+3];
    float wa1x = sA1[k], wa1y = sA1[k+1], wa1z = sA1[k+2], wa1w = sA1[k+3];
    float wb0x = sB0[k], wb0y = sB0[k+1], wb0z = sB0[k+2], wb0w = sB0[k+3];
    float wb1x = sB1[k], wb1y = sB1[k+1], wb1z = sB1[k+2], wb1w = sB1[k+3];

    #pragma unroll
    for (int r = 0; r < NODES_PER_WARP; ++r) {
        int node = node0 + r;
        if (node >= n_nodes) break;
        float a0 = x[r].x * wa0x + x[r].y * wa0y + x[r].z * wa0z + x[r].w * wa0w;
        float a1 = x[r].x * wa1x + x[r].y * wa1y + x[r].z * wa1z + x[r].w * wa1w;
        float c0 = x[r].x * wb0x + x[r].y * wb0y + x[r].z * wb0z + x[r].w * wb0w;
        float c1 = x[r].x * wb1x + x[r].y * wb1y + x[r].z * wb1z + x[r].w * wb1w;
        #pragma unroll
        for (int o = 16; o; o >>= 1) {
            a0 += __shfl_xor_sync(0xffffffffu, a0, o);
            a1 += __shfl_xor_sync(0xffffffffu, a1, o);
            c0 += __shfl_xor_sync(0xffffffffu, c0, o);
            c1 += __shfl_xor_sync(0xffffffffu, c1, o);
        }
        if (lane == 0) g_P[node] = make_float4(a0, a1, c0, c1);
    }
}

// ---------------------------------------------------------------------------
// Kernel C: per-edge gather + 2-class softmax. g_P (1.6 MB) is L2-resident,
// so random gathers are L2 hits; HBM traffic is edges + output only.
// ---------------------------------------------------------------------------
__global__ void __launch_bounds__(256) edge_kernel(const void* __restrict__ edges,
                                                   float2* __restrict__ out,
                                                   int n_edges)
{
    int e = blockIdx.x * blockDim.x + threadIdx.x;
    if (e >= n_edges) return;

    int s, d;
    if (g_is64) {
        const long long* E = (const long long*)edges;
        s = (int)E[e];
        d = (int)E[e + n_edges];
    } else {
        const int* E = (const int*)edges;
        s = E[e];
        d = E[e + n_edges];
    }

    float4 ps = __ldg(&g_P[s]);
    float4 pd = __ldg(&g_P[d]);
    float l0 = ps.x + pd.z + g_bc[0];
    float l1 = ps.y + pd.w + g_bc[1];

    float m  = fmaxf(l0, l1);
    float e0 = __expf(l0 - m);
    float e1 = __expf(l1 - m);
    float inv = 1.0f / (e0 + e1);
    out[e] = make_float2(e0 * inv, e1 * inv);
}

// ---------------------------------------------------------------------------
// Launch. metadata order:
//   0: node_features_after_gcn (float32, N_NODES*128)
//   1: edges                   (int64 or int32, 2*N_EDGES)
//   2: W1 (256*512)  3: b1 (512)  4: W2 (512*2)  5: b2 (2)
// ---------------------------------------------------------------------------
extern "C" void kernel_launch(void* const* d_in, const int* in_sizes, int n_in,
                              void* d_out, int out_size)
{
    const float* feat  = (const float*)d_in[0];
    const void*  edges = d_in[1];
    const float* W1    = (const float*)d_in[2];
    const float* b1    = (const float*)d_in[3];
    const float* W2    = (const float*)d_in[4];
    const float* b2    = (const float*)d_in[5];

    int n_nodes = in_sizes[0] / HIDDEN;
    if (n_nodes > MAX_NODES) n_nodes = MAX_NODES;
    int n_edges = in_sizes[1] / 2;

    combine_kernel<<<(515 * 32 + 255) / 256, 256>>>(
        W1, b1, W2, b2, (const long long*)edges, n_edges);

    node_kernel<<<(n_nodes + NODES_PER_BLOCK - 1) / NODES_PER_BLOCK, 256>>>(feat, n_nodes);

    edge_kernel<<<(n_edges + 255) / 256, 256>>>(edges, (float2*)d_out, n_edges);
}